// round 15
// baseline (speedup 1.0000x reference)
#include <cuda_runtime.h>
#include <cstdint>

// VN_Attention: B=8, C=64, U=3, N=512
// R15 (de-risked after 3 lost rounds):
//  K1: TCOUT=4 c-tiled projections, bounds(256,4) -> 64 regs, NO spills
//      (R9's 27us K1 was hot-loop spill under a 42-reg cap).
//      SoA kvg [slab][comp:6][jpair:256] -> fully coalesced writes.
//  K2: IDENTICAL to R9's measured 45.5us kernel (bounds(256,6), q=2/thread,
//      j-pair f32x2 packs, 2-CTA cluster over j-halves, DSMEM partials).

#define BB 8
#define CC 64
#define UU 3
#define NN 512
#define SLAB (UU * NN)          // 1536 floats
#define SLAB2 (SLAB / 2)        // 768 ull
#define NSLAB (BB * CC)         // 512
#define TCOUT 4
#define KVU 1536                // ull per slab in kvg (6 comps * 256 jpairs)

typedef unsigned long long ull;
typedef unsigned int u32;

__device__ float qg[NSLAB * SLAB];          // 3 MB, pre-scaled q, [slab][u][n]
__device__ ull kvg[(size_t)NSLAB * KVU];    // 6 MB, [slab][comp][jpair]

__device__ __forceinline__ float ex2_approx(float x) {
    float r; asm("ex2.approx.ftz.f32 %0, %1;" : "=f"(r) : "f"(x)); return r;
}
__device__ __forceinline__ ull pack2(float lo, float hi) {
    ull r; asm("mov.b64 %0, {%1, %2};" : "=l"(r) : "f"(lo), "f"(hi)); return r;
}
__device__ __forceinline__ void unpack2(ull v, float& lo, float& hi) {
    asm("mov.b64 {%0, %1}, %2;" : "=f"(lo), "=f"(hi) : "l"(v));
}
__device__ __forceinline__ ull fma2(ull a, ull b, ull c) {
    ull d; asm("fma.rn.f32x2 %0, %1, %2, %3;" : "=l"(d) : "l"(a), "l"(b), "l"(c)); return d;
}
__device__ __forceinline__ ull mul2(ull a, ull b) {
    ull d; asm("mul.rn.f32x2 %0, %1, %2;" : "=l"(d) : "l"(a), "l"(b)); return d;
}
__device__ __forceinline__ ull add2(ull a, ull b) {
    ull d; asm("add.rn.f32x2 %0, %1, %2;" : "=l"(d) : "l"(a), "l"(b)); return d;
}
__device__ __forceinline__ u32 smem_u32(const void* p) {
    u32 a;
    asm("{ .reg .u64 t; cvta.to.shared.u64 t, %1; cvt.u32.u64 %0, t; }" : "=r"(a) : "l"(p));
    return a;
}

// ---- K1: projections. grid (8*16, 3) = (b, ctile) x u-plane, 256 thr. ----
__global__ __launch_bounds__(256, 4)
void vn_proj_kernel(const float* __restrict__ x,
                    const float* __restrict__ Wq,
                    const float* __restrict__ Wk,
                    const float* __restrict__ Wv)
{
    __shared__ ull wqd[TCOUT][CC], wkd[TCOUT][CC], wvd[TCOUT][CC];  // 6 KB dup
    const int tid = threadIdx.x;
    const int bx = blockIdx.x;
    const int b  = bx >> 4;
    const int c0 = (bx & 15) * TCOUT;
    const int u  = blockIdx.y;

    {   // 256 threads load the 4x64 weight tiles, lane-duplicated.
        const int co = tid >> 6, ci = tid & 63;
        float w = Wq[(c0 + co) * CC + ci]; wqd[co][ci] = pack2(w, w);
        w = Wk[(c0 + co) * CC + ci];       wkd[co][ci] = pack2(w, w);
        w = Wv[(c0 + co) * CC + ci];       wvd[co][ci] = pack2(w, w);
    }
    __syncthreads();

    ull aq[TCOUT], ak[TCOUT], av[TCOUT];
    #pragma unroll
    for (int co = 0; co < TCOUT; ++co) { aq[co] = 0ull; ak[co] = 0ull; av[co] = 0ull; }

    const ull* xp = reinterpret_cast<const ull*>(x)
                  + (size_t)b * CC * SLAB2 + u * 256 + tid;
    #pragma unroll 4
    for (int ci = 0; ci < CC; ++ci) {
        const ull xv = xp[(size_t)ci * SLAB2];
        #pragma unroll
        for (int co = 0; co < TCOUT; ++co) {
            aq[co] = fma2(xv, wqd[co][ci], aq[co]);
            ak[co] = fma2(xv, wkd[co][ci], ak[co]);
            av[co] = fma2(xv, wvd[co][ci], av[co]);
        }
    }

    const float qs = 0.125f * 1.44269504088896340736f;  // C^-0.5 * log2(e)
    const ull qs2 = pack2(qs, qs);
    #pragma unroll
    for (int co = 0; co < TCOUT; ++co) {
        const int slab = b * CC + c0 + co;
        // q: [slab][u][n], coalesced.
        reinterpret_cast<ull*>(qg)[(size_t)slab * SLAB2 + u * 256 + tid]
            = mul2(aq[co], qs2);
        // kv SoA: comp u = k_u j-pairs, comp 3+u = v_u j-pairs. Coalesced runs.
        kvg[(size_t)slab * KVU + (u)     * 256 + tid] = ak[co];
        kvg[(size_t)slab * KVU + (3 + u) * 256 + tid] = av[co];
    }
}

// ---- K2: attention. q=2/thread, j-pair packs, 2-CTA cluster over j-halves. --
__global__ __launch_bounds__(256, 6) __cluster_dims__(2, 1, 1)
void vn_attn_kernel(const float* __restrict__ x,
                    float* __restrict__ out)
{
    __shared__ __align__(16) ull kv[128 * 6];        // 6 KB: 128 interleaved rows
    __shared__ __align__(16) float4 pbuf[NN];        // 8 KB partials

    const int tid = threadIdx.x;
    const int bc = blockIdx.x >> 1;
    u32 z;                                           // j-half == cluster rank
    asm("mov.u32 %0, %%cluster_ctarank;" : "=r"(z));

    // Stage: global SoA [comp][jpair] -> smem interleaved [jp][comp].
    {
        const ull* src = kvg + (size_t)bc * KVU + z * 128;
        #pragma unroll
        for (int k = 0; k < 3; ++k) {
            const int idx = tid + k * 256;           // 0..767
            const int comp = idx >> 7;               // 0..5
            const int jp   = idx & 127;
            kv[jp * 6 + comp] = src[comp * 256 + jp];
        }
    }

    // Queries i0 = tid, i1 = tid+256 (pre-scaled q from K1).
    const float* qb = qg + (size_t)bc * SLAB;
    const int i0 = tid, i1 = tid + 256;
    const ull q00 = pack2(qb[0 * NN + i0], qb[0 * NN + i0]);
    const ull q01 = pack2(qb[1 * NN + i0], qb[1 * NN + i0]);
    const ull q02 = pack2(qb[2 * NN + i0], qb[2 * NN + i0]);
    const ull q10 = pack2(qb[0 * NN + i1], qb[0 * NN + i1]);
    const ull q11 = pack2(qb[1 * NN + i1], qb[1 * NN + i1]);
    const ull q12 = pack2(qb[2 * NN + i1], qb[2 * NN + i1]);
    __syncthreads();

    ull s0 = 0ull, a00 = 0ull, a01 = 0ull, a02 = 0ull;
    ull s1 = 0ull, a10 = 0ull, a11 = 0ull, a12 = 0ull;

    const ulonglong2* kvrow = reinterpret_cast<const ulonglong2*>(kv);
    #pragma unroll 4
    for (int p = 0; p < 128; ++p) {
        const ulonglong2 A = kvrow[p * 3 + 0];   // (k0,k1) j-pairs
        const ulonglong2 B = kvrow[p * 3 + 1];   // (k2,v0)
        const ulonglong2 C = kvrow[p * 3 + 2];   // (v1,v2)

        ull d0 = fma2(q00, A.x, fma2(q01, A.y, mul2(q02, B.x)));
        ull d1 = fma2(q10, A.x, fma2(q11, A.y, mul2(q12, B.x)));

        float d0l, d0h, d1l, d1h;
        unpack2(d0, d0l, d0h);
        unpack2(d1, d1l, d1h);
        const ull e0 = pack2(ex2_approx(d0l), ex2_approx(d0h));
        const ull e1 = pack2(ex2_approx(d1l), ex2_approx(d1h));

        s0 = add2(s0, e0);
        a00 = fma2(e0, B.y, a00);
        a01 = fma2(e0, C.x, a01);
        a02 = fma2(e0, C.y, a02);

        s1 = add2(s1, e1);
        a10 = fma2(e1, B.y, a10);
        a11 = fma2(e1, C.x, a11);
        a12 = fma2(e1, C.y, a12);
    }

    // Reduce packed j-halves -> per-query partial (s, a0, a1, a2).
    float lo, hi;
    float4 p0, p1;
    unpack2(s0, lo, hi);  p0.x = lo + hi;
    unpack2(a00, lo, hi); p0.y = lo + hi;
    unpack2(a01, lo, hi); p0.z = lo + hi;
    unpack2(a02, lo, hi); p0.w = lo + hi;
    unpack2(s1, lo, hi);  p1.x = lo + hi;
    unpack2(a10, lo, hi); p1.y = lo + hi;
    unpack2(a11, lo, hi); p1.z = lo + hi;
    unpack2(a12, lo, hi); p1.w = lo + hi;
    pbuf[i0] = p0;
    pbuf[i1] = p1;

    // Cluster barrier: partials visible to peer.
    asm volatile("barrier.cluster.arrive.aligned;" ::: "memory");
    asm volatile("barrier.cluster.wait.aligned;" ::: "memory");

    // Epilogue: finalize queries [z*256, z*256+256).
    const int jq = (int)z * 256 + tid;
    const float4 mine = pbuf[jq];
    float4 theirs;
    {
        u32 laddr = smem_u32(&pbuf[jq]);
        u32 raddr;
        asm("mapa.shared::cluster.u32 %0, %1, %2;" : "=r"(raddr) : "r"(laddr), "r"(z ^ 1u));
        asm("ld.shared::cluster.v4.f32 {%0,%1,%2,%3}, [%4];"
            : "=f"(theirs.x), "=f"(theirs.y), "=f"(theirs.z), "=f"(theirs.w)
            : "r"(raddr));
    }

    const float inv = __fdividef(1.f, mine.x + theirs.x);
    const size_t base = (size_t)bc * SLAB;
    out[base + 0 * NN + jq] = x[base + 0 * NN + jq] + (mine.y + theirs.y) * inv;
    out[base + 1 * NN + jq] = x[base + 1 * NN + jq] + (mine.z + theirs.z) * inv;
    out[base + 2 * NN + jq] = x[base + 2 * NN + jq] + (mine.w + theirs.w) * inv;

    // Keep smem alive until peer finished reading.
    asm volatile("barrier.cluster.arrive.aligned;" ::: "memory");
    asm volatile("barrier.cluster.wait.aligned;" ::: "memory");
}

extern "C" void kernel_launch(void* const* d_in, const int* in_sizes, int n_in,
                              void* d_out, int out_size) {
    const float* x  = (const float*)d_in[0];
    const float* Wq = (const float*)d_in[1];
    const float* Wk = (const float*)d_in[2];
    const float* Wv = (const float*)d_in[3];
    float* out = (float*)d_out;

    dim3 grid1(BB * (CC / TCOUT), UU);
    vn_proj_kernel<<<grid1, 256>>>(x, Wq, Wk, Wv);
    vn_attn_kernel<<<NSLAB * 2, 256>>>(x, out);
}